// round 11
// baseline (speedup 1.0000x reference)
#include <cuda_runtime.h>

#define BATCH 4096
#define SEQ   64
#define HID   256
#define NHEAD 4
#define HDIM  64
#define THREADS 512

// padded smem strides (floats) — chosen so 4-rows-per-instruction LDS.128
// patterns hit distinct banks (row*stride*4B % 128 != 0)
#define XSTR 260   // xs / att
#define QSTR 68    // qh
#define KSTR 65    // kh (scalar-read pattern, conflict-free with lane map)
#define SSTR 68    // sc

typedef unsigned long long ull;

__device__ __forceinline__ ull pack2(float lo, float hi) {
    ull r; asm("mov.b64 %0, {%1, %2};" : "=l"(r) : "f"(lo), "f"(hi)); return r;
}
__device__ __forceinline__ float2 unpack2(ull v) {
    float2 f; asm("mov.b64 {%0, %1}, %2;" : "=f"(f.x), "=f"(f.y) : "l"(v)); return f;
}
__device__ __forceinline__ void fma2(ull& d, ull a, ull b) {
    asm("fma.rn.f32x2 %0, %1, %2, %0;" : "+l"(d) : "l"(a), "l"(b));
}

// Transposed weights [k][n] so GEMM loads are coalesced across n.
__device__ float g_WT[4][HID * HID];

__global__ void prep_transpose(const float* __restrict__ Wq, const float* __restrict__ Wk,
                               const float* __restrict__ Wv, const float* __restrict__ Wo) {
    int idx = blockIdx.x * blockDim.x + threadIdx.x;
    int k = idx >> 8, n = idx & 255;
    g_WT[0][idx] = Wq[n * HID + k];
    g_WT[1][idx] = Wk[n * HID + k];
    g_WT[2][idx] = Wv[n * HID + k];
    g_WT[3][idx] = Wo[n * HID + k];
}

// smem floats:
//   xs   64*260 = 16640
//   qh   64*68  =  4352
//   kh   64*65  =  4160
//   vh   64*64  =  4096
//   sc   64*68  =  4352
//   att  64*260 = 16640
//   asum 64*64  =  4096
// total 54336 floats = 217344 B  (< 227 KB cap)
#define SMEM_FLOATS (SEQ*XSTR + SEQ*QSTR + SEQ*KSTR + SEQ*HDIM + SEQ*SSTR + SEQ*XSTR + SEQ*SEQ)

__global__ void __launch_bounds__(THREADS, 1)
fused_kernel(const float* __restrict__ x,
             const float* __restrict__ bq, const float* __restrict__ bk,
             const float* __restrict__ bv, const float* __restrict__ bo,
             const float* __restrict__ ln_g, const float* __restrict__ ln_b,
             float* __restrict__ out, float* __restrict__ attn_out)
{
    extern __shared__ float smf[];
    float* xs   = smf;
    float* qh   = xs + SEQ * XSTR;
    float* kh   = qh + SEQ * QSTR;
    float* vh   = kh + SEQ * KSTR;
    float* sc   = vh + SEQ * HDIM;
    float* att  = sc + SEQ * SSTR;
    float* asum = att + SEQ * XSTR;
    float* ybuf = qh;   // outproj output [64][HID]=16384 fl <= qh+kh+vh+sc (16960 fl)

    const int b   = blockIdx.x;
    const int t   = threadIdx.x;
    const int w   = t >> 5, ln = t & 31;
    const int ch  = w & 1;          // column half of the 64-col head space
    const int rb  = w >> 1;         // row block (8 rows)
    const int tc8 = ln & 7, tr4 = ln >> 3;
    const int c0  = 32 * ch + 4 * tc8;   // 4 cols
    const int r0  = 8 * rb + 2 * tr4;    // 2 rows

    // ---- stage x (padded rows), zero asum ----
    {
        const float4* src = (const float4*)(x + (size_t)b * SEQ * HID);
        float4* dst = (float4*)xs;                  // 65 float4 per padded row
        #pragma unroll
        for (int i = 0; i < 8; i++) {
            int f = t + THREADS * i;                // 4096 source float4
            dst[(f >> 6) * 65 + (f & 63)] = src[f];
        }
        float4 z = make_float4(0.f, 0.f, 0.f, 0.f);
        float4* az = (float4*)asum;
        az[t] = z; az[t + THREADS] = z;
    }
    __syncthreads();

    for (int h = 0; h < NHEAD; h++) {
        // ---- fused Q/K/V projection: warp covers rows 8rb..+7 x cols 32ch..+31 ----
        ull aq[2][2], ak[2][2], av[2][2];
        #pragma unroll
        for (int i = 0; i < 2; i++) {
            aq[i][0] = aq[i][1] = 0ull;
            ak[i][0] = ak[i][1] = 0ull;
            av[i][0] = av[i][1] = 0ull;
        }
        const float* wq = g_WT[0] + h * HDIM + c0;
        const float* wk = g_WT[1] + h * HDIM + c0;
        const float* wv = g_WT[2] + h * HDIM + c0;
        for (int k = 0; k < HID; k += 4) {
            float4 wqv[4], wkv[4], wvv[4], xv4[2];
            #pragma unroll
            for (int kk = 0; kk < 4; kk++) wqv[kk] = *(const float4*)(wq + (k + kk) * HID);
            #pragma unroll
            for (int kk = 0; kk < 4; kk++) wkv[kk] = *(const float4*)(wk + (k + kk) * HID);
            #pragma unroll
            for (int kk = 0; kk < 4; kk++) wvv[kk] = *(const float4*)(wv + (k + kk) * HID);
            #pragma unroll
            for (int i = 0; i < 2; i++)  xv4[i] = *(const float4*)&xs[(r0 + i) * XSTR + k];

            float xv[2][4];
            #pragma unroll
            for (int i = 0; i < 2; i++) {
                xv[i][0] = xv4[i].x; xv[i][1] = xv4[i].y;
                xv[i][2] = xv4[i].z; xv[i][3] = xv4[i].w;
            }
            #pragma unroll
            for (int kk = 0; kk < 4; kk++) {
                ull q01 = pack2(wqv[kk].x, wqv[kk].y), q23 = pack2(wqv[kk].z, wqv[kk].w);
                ull k01 = pack2(wkv[kk].x, wkv[kk].y), k23 = pack2(wkv[kk].z, wkv[kk].w);
                ull v01 = pack2(wvv[kk].x, wvv[kk].y), v23 = pack2(wvv[kk].z, wvv[kk].w);
                #pragma unroll
                for (int i = 0; i < 2; i++) {
                    ull xx = pack2(xv[i][kk], xv[i][kk]);
                    fma2(aq[i][0], xx, q01); fma2(aq[i][1], xx, q23);
                    fma2(ak[i][0], xx, k01); fma2(ak[i][1], xx, k23);
                    fma2(av[i][0], xx, v01); fma2(av[i][1], xx, v23);
                }
            }
        }
        {
            float4 bq4 = *(const float4*)(bq + h * HDIM + c0);
            float4 bk4 = *(const float4*)(bk + h * HDIM + c0);
            float4 bv4 = *(const float4*)(bv + h * HDIM + c0);
            #pragma unroll
            for (int i = 0; i < 2; i++) {
                float2 a = unpack2(aq[i][0]), c = unpack2(aq[i][1]);
                *(float4*)&qh[(r0 + i) * QSTR + c0] =
                    make_float4(a.x + bq4.x, a.y + bq4.y, c.x + bq4.z, c.y + bq4.w);
                a = unpack2(ak[i][0]); c = unpack2(ak[i][1]);
                kh[(r0 + i) * KSTR + c0 + 0] = a.x + bk4.x;
                kh[(r0 + i) * KSTR + c0 + 1] = a.y + bk4.y;
                kh[(r0 + i) * KSTR + c0 + 2] = c.x + bk4.z;
                kh[(r0 + i) * KSTR + c0 + 3] = c.y + bk4.w;
                a = unpack2(av[i][0]); c = unpack2(av[i][1]);
                *(float4*)&vh[(r0 + i) * HDIM + c0] =
                    make_float4(a.x + bv4.x, a.y + bv4.y, c.x + bv4.z, c.y + bv4.w);
            }
        }
        __syncthreads();   // qh/kh/vh read cross-warp below

        // ---- scores = Q @ K^T * 0.125 ----
        {
            ull s01[2], s23[2];
            #pragma unroll
            for (int i = 0; i < 2; i++) { s01[i] = 0ull; s23[i] = 0ull; }
            for (int d = 0; d < HDIM; d += 4) {
                float qv[2][4];
                #pragma unroll
                for (int i = 0; i < 2; i++) {
                    float4 q4 = *(const float4*)&qh[(r0 + i) * QSTR + d];
                    qv[i][0] = q4.x; qv[i][1] = q4.y; qv[i][2] = q4.z; qv[i][3] = q4.w;
                }
                #pragma unroll
                for (int dd = 0; dd < 4; dd++) {
                    float k0 = kh[(c0 + 0) * KSTR + d + dd], k1 = kh[(c0 + 1) * KSTR + d + dd];
                    float k2 = kh[(c0 + 2) * KSTR + d + dd], k3 = kh[(c0 + 3) * KSTR + d + dd];
                    ull k01 = pack2(k0, k1), k23 = pack2(k2, k3);
                    #pragma unroll
                    for (int i = 0; i < 2; i++) {
                        ull qq = pack2(qv[i][dd], qv[i][dd]);
                        fma2(s01[i], qq, k01);
                        fma2(s23[i], qq, k23);
                    }
                }
            }
            #pragma unroll
            for (int i = 0; i < 2; i++) {
                float2 a = unpack2(s01[i]), c = unpack2(s23[i]);
                *(float4*)&sc[(r0 + i) * SSTR + c0] =
                    make_float4(a.x * 0.125f, a.y * 0.125f, c.x * 0.125f, c.y * 0.125f);
            }
        }
        // sc rows 8rb..+7 are produced by the warp PAIR (2rb, 2rb+1) — pair barrier
        asm volatile("bar.sync %0, %1;" :: "r"(rb + 1), "r"(64) : "memory");

        // ---- softmax: warp w owns rows 4w..4w+3 ----
        #pragma unroll
        for (int j = 0; j < 4; j++) {
            int q = 4 * w + j;
            float s0 = sc[q * SSTR + ln], s1 = sc[q * SSTR + ln + 32];
            float m = fmaxf(s0, s1);
            #pragma unroll
            for (int o = 16; o > 0; o >>= 1) m = fmaxf(m, __shfl_xor_sync(0xffffffffu, m, o));
            float e0 = __expf(s0 - m), e1 = __expf(s1 - m);
            float sum = e0 + e1;
            #pragma unroll
            for (int o = 16; o > 0; o >>= 1) sum += __shfl_xor_sync(0xffffffffu, sum, o);
            float inv = 1.0f / sum;
            float a0 = e0 * inv, a1 = e1 * inv;
            sc[q * SSTR + ln]      = a0;
            sc[q * SSTR + ln + 32] = a1;
            asum[q * SEQ + ln]      += 0.25f * a0;
            asum[q * SEQ + ln + 32] += 0.25f * a1;
        }
        asm volatile("bar.sync %0, %1;" :: "r"(rb + 1), "r"(64) : "memory");

        // ---- attended[:, 64h + cols] = attn @ V ----
        {
            ull a01[2], a23[2];
            #pragma unroll
            for (int i = 0; i < 2; i++) { a01[i] = 0ull; a23[i] = 0ull; }
            for (int kk = 0; kk < SEQ; kk += 4) {
                float4 vv[4];
                #pragma unroll
                for (int k2 = 0; k2 < 4; k2++)
                    vv[k2] = *(const float4*)&vh[(kk + k2) * HDIM + c0];
                float pv[2][4];
                #pragma unroll
                for (int i = 0; i < 2; i++) {
                    float4 p4 = *(const float4*)&sc[(r0 + i) * SSTR + kk];
                    pv[i][0] = p4.x; pv[i][1] = p4.y; pv[i][2] = p4.z; pv[i][3] = p4.w;
                }
                #pragma unroll
                for (int k2 = 0; k2 < 4; k2++) {
                    ull v01 = pack2(vv[k2].x, vv[k2].y), v23 = pack2(vv[k2].z, vv[k2].w);
                    #pragma unroll
                    for (int i = 0; i < 2; i++) {
                        ull pp = pack2(pv[i][k2], pv[i][k2]);
                        fma2(a01[i], pp, v01);
                        fma2(a23[i], pp, v23);
                    }
                }
            }
            #pragma unroll
            for (int i = 0; i < 2; i++) {
                float2 a = unpack2(a01[i]), c = unpack2(a23[i]);
                *(float4*)&att[(r0 + i) * XSTR + h * HDIM + c0] =
                    make_float4(a.x, a.y, c.x, c.y);
            }
        }
        __syncthreads();   // next head overwrites qh/kh/vh (cross-warp readers)
    }

    // ---- output projection + residual ----
    const float* wo = g_WT[3];
    for (int cg = 0; cg < 4; cg++) {
        int cc = 64 * cg + c0;
        ull ac[2][2];
        #pragma unroll
        for (int i = 0; i < 2; i++) ac[i][0] = ac[i][1] = 0ull;
        for (int k = 0; k < HID; k += 4) {
            float4 w4[4], a4[2];
            #pragma unroll
            for (int kk = 0; kk < 4; kk++)
                w4[kk] = *(const float4*)(wo + (k + kk) * HID + cc);
            #pragma unroll
            for (int i = 0; i < 2; i++)
                a4[i] = *(const float4*)&att[(r0 + i) * XSTR + k];
            float av4[2][4];
            #pragma unroll
            for (int i = 0; i < 2; i++) {
                av4[i][0] = a4[i].x; av4[i][1] = a4[i].y;
                av4[i][2] = a4[i].z; av4[i][3] = a4[i].w;
            }
            #pragma unroll
            for (int kk = 0; kk < 4; kk++) {
                ull w01 = pack2(w4[kk].x, w4[kk].y), w23 = pack2(w4[kk].z, w4[kk].w);
                #pragma unroll
                for (int i = 0; i < 2; i++) {
                    ull aa = pack2(av4[i][kk], av4[i][kk]);
                    fma2(ac[i][0], aa, w01);
                    fma2(ac[i][1], aa, w23);
                }
            }
        }
        float4 bo4 = *(const float4*)(bo + cc);
        #pragma unroll
        for (int i = 0; i < 2; i++) {
            float2 a = unpack2(ac[i][0]), c = unpack2(ac[i][1]);
            float4 xr = *(const float4*)&xs[(r0 + i) * XSTR + cc];
            *(float4*)&ybuf[(r0 + i) * HID + cc] =
                make_float4(a.x + bo4.x + xr.x, a.y + bo4.y + xr.y,
                            c.x + bo4.z + xr.z, c.y + bo4.w + xr.w);
        }
    }
    __syncthreads();       // LN row-ownership (4w..4w+3) differs from outproj rows

    // ---- LayerNorm rows 4w..4w+3, lane owns 8 contiguous cols ----
    {
        float* ob = out + (size_t)b * SEQ * HID;
        const int cb = 8 * ln;
        const float4 g0  = *(const float4*)(ln_g + cb);
        const float4 g1  = *(const float4*)(ln_g + cb + 4);
        const float4 be0 = *(const float4*)(ln_b + cb);
        const float4 be1 = *(const float4*)(ln_b + cb + 4);
        #pragma unroll
        for (int j = 0; j < 4; j++) {
            int r = 4 * w + j;
            float4 va = *(const float4*)&ybuf[r * HID + cb];
            float4 vb = *(const float4*)&ybuf[r * HID + cb + 4];
            float s  = (va.x + va.y) + (va.z + va.w) + (vb.x + vb.y) + (vb.z + vb.w);
            float ss = va.x * va.x + va.y * va.y + va.z * va.z + va.w * va.w
                     + vb.x * vb.x + vb.y * vb.y + vb.z * vb.z + vb.w * vb.w;
            #pragma unroll
            for (int o = 16; o > 0; o >>= 1) {
                s  += __shfl_xor_sync(0xffffffffu, s, o);
                ss += __shfl_xor_sync(0xffffffffu, ss, o);
            }
            float mu  = s * (1.0f / HID);
            float var = ss * (1.0f / HID) - mu * mu;
            float rstd = rsqrtf(var + 1e-5f);
            float4 o0, o1;
            o0.x = (va.x - mu) * rstd * g0.x + be0.x;
            o0.y = (va.y - mu) * rstd * g0.y + be0.y;
            o0.z = (va.z - mu) * rstd * g0.z + be0.z;
            o0.w = (va.w - mu) * rstd * g0.w + be0.w;
            o1.x = (vb.x - mu) * rstd * g1.x + be1.x;
            o1.y = (vb.y - mu) * rstd * g1.y + be1.y;
            o1.z = (vb.z - mu) * rstd * g1.z + be1.z;
            o1.w = (vb.w - mu) * rstd * g1.w + be1.w;
            *(float4*)&ob[r * HID + cb]     = o0;
            *(float4*)&ob[r * HID + cb + 4] = o1;
        }
    }

    // ---- store attn average rows 4w..4w+3 (asum rows are warp-local) ----
    {
        float4* dst = (float4*)(attn_out + (size_t)b * SEQ * SEQ);
        const float4* src = (const float4*)asum;
        #pragma unroll
        for (int i = 0; i < 2; i++) {
            int idx = 64 * w + ln + 32 * i;
            dst[idx] = src[idx];
        }
    }
}

extern "C" void kernel_launch(void* const* d_in, const int* in_sizes, int n_in,
                              void* d_out, int out_size) {
    const float* x    = (const float*)d_in[0];
    const float* Wq   = (const float*)d_in[1];
    const float* bq   = (const float*)d_in[2];
    const float* Wk   = (const float*)d_in[3];
    const float* bk   = (const float*)d_in[4];
    const float* Wv   = (const float*)d_in[5];
    const float* bv   = (const float*)d_in[6];
    const float* Wo   = (const float*)d_in[7];
    const float* bo   = (const float*)d_in[8];
    const float* g    = (const float*)d_in[9];
    const float* bt   = (const float*)d_in[10];

    float* out      = (float*)d_out;
    float* attn_out = out + (size_t)BATCH * SEQ * HID;

    const int smem_bytes = SMEM_FLOATS * (int)sizeof(float);
    cudaFuncSetAttribute(fused_kernel, cudaFuncAttributeMaxDynamicSharedMemorySize, smem_bytes);

    prep_transpose<<<256, 256>>>(Wq, Wk, Wv, Wo);
    fused_kernel<<<BATCH, THREADS, smem_bytes>>>(x, bq, bk, bv, bo, g, bt, out, attn_out);
}